// round 1
// baseline (speedup 1.0000x reference)
#include <cuda_runtime.h>

// Problem constants (B=4, 96^3 vol, 4^3 patches, E=768)
#define TOKENS   13824      // 24*24*24
#define MASKN    10368      // 75%
#define UNMASKN  3456
#define EDIM     768
#define KDIM     64
#define TT       16         // tokens per block
#define NTHREADS 256
#define UTILES   (UNMASKN / TT)   // 216
#define MTILES   (MASKN / TT)     // 648
#define BATCH    4
#define LOG2_1E4 13.287712379549449f

__device__ __forceinline__ unsigned long long pack2(float a) {
    unsigned long long r;
    asm("mov.b64 %0, {%1, %1};" : "=l"(r) : "f"(a));
    return r;
}
__device__ __forceinline__ void fma2(unsigned long long& acc,
                                     unsigned long long a, unsigned long long b) {
    asm("fma.rn.f32x2 %0, %1, %2, %0;" : "+l"(acc) : "l"(a), "l"(b));
}
__device__ __forceinline__ void unpack2(unsigned long long v, float& lo, float& hi) {
    asm("mov.b64 {%0, %1}, %2;" : "=f"(lo), "=f"(hi) : "l"(v));
}

// One block = 16 tokens x full 768 embed dims (GEMM K=64 + bias + posenc + LayerNorm fused).
// Blocks [0, 864): unmask tokens (per batch). Blocks [864, 1512): mask tokens,
// computed once and written to all 4 batches (batch-invariant incl. LN).
__global__ __launch_bounds__(NTHREADS)
void embed_kernel(const float* __restrict__ x,
                  const float* __restrict__ W,
                  const float* __restrict__ bias,
                  const float* __restrict__ mtok,
                  const float* __restrict__ gamma,
                  const float* __restrict__ beta,
                  const int*   __restrict__ perm,
                  float* __restrict__ out)
{
    __shared__ float ps[KDIM][TT];          // patch tile, k-major so token pairs are contiguous
    __shared__ int   sH[TT], sW[TT], sD[TT];
    __shared__ float redS[TT][9], redQ[TT][9];
    __shared__ float meanv[TT], rstdv[TT];

    const int tid = threadIdx.x;
    const int bi  = blockIdx.x;
    const bool is_mask = bi >= BATCH * UTILES;
    int b = 0, tile;
    if (!is_mask) { b = bi / UTILES; tile = bi % UTILES; }
    else          { tile = bi - BATCH * UTILES; }

    // ---- stage: gather 16 patch rows (64 floats each) into SMEM ----
    {
        const int tok = tid >> 4;     // 0..15
        const int seg = tid & 15;     // 0..15 -> 4 floats each
        const int m   = tile * TT + tok;
        const int s   = is_mask ? perm[m] : perm[MASKN + m];
        const int h = s / 576, w = (s % 576) / 24, d = s % 24;
        if (seg == 0) { sH[tok] = h; sW[tok] = w; sD[tok] = d; }
        float4 v;
        if (!is_mask) {
            const int i = seg >> 2, j = seg & 3;
            const size_t xi = (((size_t)(b * 96 + 4 * h + i)) * 96 + (4 * w + j)) * 96 + 4 * d;
            v = *(const float4*)(x + xi);
        } else {
            v = *(const float4*)(mtok + (size_t)m * KDIM + seg * 4);
        }
        const int p = seg * 4;
        ps[p + 0][tok] = v.x; ps[p + 1][tok] = v.y;
        ps[p + 2][tok] = v.z; ps[p + 3][tok] = v.w;
    }
    __syncthreads();

    // ---- GEMM: each thread owns embed dims {tid, tid+256, tid+512},
    //      accumulators hold token PAIRS in packed f32x2 ----
    unsigned long long a0[8], a1[8], a2[8];
    #pragma unroll
    for (int t = 0; t < 8; t++) { a0[t] = 0ull; a1[t] = 0ull; a2[t] = 0ull; }

    const float* wp = W + tid;
    #pragma unroll 4
    for (int k = 0; k < KDIM; k++) {
        const unsigned long long W0 = pack2(wp[k * EDIM]);
        const unsigned long long W1 = pack2(wp[k * EDIM + 256]);
        const unsigned long long W2 = pack2(wp[k * EDIM + 512]);
        const unsigned long long* pp = (const unsigned long long*)ps[k];
        #pragma unroll
        for (int t = 0; t < 8; t++) {
            const unsigned long long pd = pp[t];   // LDS.64 broadcast (token pair)
            fma2(a0[t], pd, W0);
            fma2(a1[t], pd, W1);
            fma2(a2[t], pd, W2);
        }
    }

    // ---- epilogue: unpack, + bias + positional encoding ----
    float v0[TT], v1[TT], v2[TT];
    #pragma unroll
    for (int t = 0; t < 8; t++) {
        unpack2(a0[t], v0[2 * t], v0[2 * t + 1]);
        unpack2(a1[t], v1[2 * t], v1[2 * t + 1]);
        unpack2(a2[t], v2[2 * t], v2[2 * t + 1]);
    }

    const float bias0 = bias[tid], bias1 = bias[tid + 256], bias2 = bias[tid + 512];
    // channel pair index j = (e % 256) / 2 ; for e in {tid, tid+256, tid+512} it's tid>>1 always
    const float invf = exp2f(-(float)(tid >> 1) * (LOG2_1E4 / 128.0f));
    const bool even = (tid & 1) == 0;
    const int warp = tid >> 5, lane = tid & 31;

    #pragma unroll
    for (int t = 0; t < TT; t++) {
        float sv, cv;
        sincosf((float)sH[t] * invf, &sv, &cv); const float p0 = even ? sv : cv;
        sincosf((float)sW[t] * invf, &sv, &cv); const float p1 = even ? sv : cv;
        sincosf((float)sD[t] * invf, &sv, &cv); const float p2 = even ? sv : cv;
        v0[t] += bias0 + p0;
        v1[t] += bias1 + p1;
        v2[t] += bias2 + p2;

        float sm = v0[t] + v1[t] + v2[t];
        float sq = v0[t] * v0[t] + v1[t] * v1[t] + v2[t] * v2[t];
        #pragma unroll
        for (int off = 16; off > 0; off >>= 1) {
            sm += __shfl_xor_sync(0xffffffffu, sm, off);
            sq += __shfl_xor_sync(0xffffffffu, sq, off);
        }
        if (lane == 0) { redS[t][warp] = sm; redQ[t][warp] = sq; }
    }
    __syncthreads();

    if (tid < TT) {
        float sm = 0.f, sq = 0.f;
        #pragma unroll
        for (int wi = 0; wi < 8; wi++) { sm += redS[tid][wi]; sq += redQ[tid][wi]; }
        const float mn = sm * (1.0f / (float)EDIM);
        const float vr = sq * (1.0f / (float)EDIM) - mn * mn;
        meanv[tid] = mn;
        rstdv[tid] = rsqrtf(vr + 0.001f);
    }
    __syncthreads();

    const float g0 = gamma[tid], g1 = gamma[tid + 256], g2 = gamma[tid + 512];
    const float be0 = beta[tid], be1 = beta[tid + 256], be2 = beta[tid + 512];

    if (!is_mask) {
        float* o = out + ((size_t)b * TOKENS + (size_t)tile * TT) * EDIM + tid;
        #pragma unroll
        for (int t = 0; t < TT; t++) {
            const float mn = meanv[t], rs = rstdv[t];
            o[(size_t)t * EDIM]       = (v0[t] - mn) * rs * g0 + be0;
            o[(size_t)t * EDIM + 256] = (v1[t] - mn) * rs * g1 + be1;
            o[(size_t)t * EDIM + 512] = (v2[t] - mn) * rs * g2 + be2;
        }
    } else {
        float* o = out + ((size_t)UNMASKN + (size_t)tile * TT) * EDIM + tid;
        const size_t bstride = (size_t)TOKENS * EDIM;
        #pragma unroll
        for (int t = 0; t < TT; t++) {
            const float mn = meanv[t], rs = rstdv[t];
            const float o0 = (v0[t] - mn) * rs * g0 + be0;
            const float o1 = (v1[t] - mn) * rs * g1 + be1;
            const float o2 = (v2[t] - mn) * rs * g2 + be2;
            #pragma unroll
            for (int bb = 0; bb < BATCH; bb++) {
                float* op = o + bb * bstride + (size_t)t * EDIM;
                op[0]   = o0;
                op[256] = o1;
                op[512] = o2;
            }
        }
    }
}

// mask_idx = perm[:MASKN] written (value-cast to float) after the main output block
__global__ void tail_kernel(const int* __restrict__ perm, float* __restrict__ o, int n) {
    const int i = blockIdx.x * blockDim.x + threadIdx.x;
    if (i < n) o[i] = (float)perm[i];
}

extern "C" void kernel_launch(void* const* d_in, const int* in_sizes, int n_in,
                              void* d_out, int out_size) {
    const float* x     = (const float*)d_in[0];
    const float* W     = (const float*)d_in[1];
    const float* bias  = (const float*)d_in[2];
    const float* mtok  = (const float*)d_in[3];
    const float* gamma = (const float*)d_in[4];
    const float* beta  = (const float*)d_in[5];
    const int*   perm  = (const int*)d_in[6];
    float* out = (float*)d_out;

    embed_kernel<<<BATCH * UTILES + MTILES, NTHREADS>>>(x, W, bias, mtok, gamma, beta, perm, out);

    const long long main_elems = (long long)BATCH * TOKENS * EDIM;  // 42,467,328
    const long long extra = (long long)out_size - main_elems;
    if (extra > 0) {
        const int n = (int)extra;   // expected 10368 (mask_idx)
        tail_kernel<<<(n + 255) / 256, 256>>>(perm, out + main_elems, n);
    }
}

// round 2
// speedup vs baseline: 1.2033x; 1.2033x over previous
#include <cuda_runtime.h>

// Problem constants (B=4, 96^3 vol, 4^3 patches, E=768)
#define TOKENS   13824      // 24*24*24
#define MASKN    10368      // 75%
#define UNMASKN  3456
#define EDIM     768
#define KDIM     64
#define TT       16         // tokens per block
#define NTHREADS 256
#define UTILES   (UNMASKN / TT)   // 216
#define MTILES   (MASKN / TT)     // 648
#define BATCH    4
#define LOG2_1E4 13.287712379549449f

// positional-encoding table: g_pe[pos][c] = (c even ? sin : cos)(pos * 10000^-( (c>>1)/128 ))
__device__ float g_pe[24][256];

__device__ __forceinline__ unsigned long long pack2(float a) {
    unsigned long long r;
    asm("mov.b64 %0, {%1, %1};" : "=l"(r) : "f"(a));
    return r;
}
__device__ __forceinline__ void fma2(unsigned long long& acc,
                                     unsigned long long a, unsigned long long b) {
    asm("fma.rn.f32x2 %0, %1, %2, %0;" : "+l"(acc) : "l"(a), "l"(b));
}
__device__ __forceinline__ void unpack2(unsigned long long v, float& lo, float& hi) {
    asm("mov.b64 {%0, %1}, %2;" : "=f"(lo), "=f"(hi) : "l"(v));
}

// Blocks [0,24): fill pe table row = blockIdx.x. Blocks [24,..): write mask_idx tail.
__global__ __launch_bounds__(NTHREADS)
void init_kernel(const int* __restrict__ perm, float* __restrict__ tail_out, int n_tail) {
    const int bi = blockIdx.x, tid = threadIdx.x;
    if (bi < 24) {
        const float invf = exp2f(-(float)(tid >> 1) * (LOG2_1E4 / 128.0f));
        float s, c;
        sincosf((float)bi * invf, &s, &c);
        g_pe[bi][tid] = (tid & 1) ? c : s;
    } else {
        const int i = (bi - 24) * NTHREADS + tid;
        if (i < n_tail) tail_out[i] = (float)perm[i];
    }
}

// One block = 16 tokens x full 768 embed dims (GEMM K=64 + bias + posenc + LayerNorm fused).
// Blocks [0, 864): unmask tokens (per batch). Blocks [864, 1512): mask tokens,
// computed once and written to all 4 batches (batch-invariant incl. LN).
__global__ __launch_bounds__(NTHREADS)
void embed_kernel(const float* __restrict__ x,
                  const float* __restrict__ W,
                  const float* __restrict__ bias,
                  const float* __restrict__ mtok,
                  const float* __restrict__ gamma,
                  const float* __restrict__ beta,
                  const int*   __restrict__ perm,
                  float* __restrict__ out)
{
    __shared__ float ps[KDIM][TT];          // patch tile, k-major so token pairs are contiguous
    __shared__ int   sH[TT], sW[TT], sD[TT];
    __shared__ float redS[TT][9], redQ[TT][9];
    __shared__ float meanv[TT], rstdv[TT];

    const int tid = threadIdx.x;
    const int bi  = blockIdx.x;
    const bool is_mask = bi >= BATCH * UTILES;
    int b = 0, tile;
    if (!is_mask) { b = bi / UTILES; tile = bi % UTILES; }
    else          { tile = bi - BATCH * UTILES; }

    // ---- stage: gather 16 patch rows (64 floats each) into SMEM ----
    {
        const int tok = tid >> 4;     // 0..15
        const int seg = tid & 15;     // 0..15 -> 4 floats each
        const int m   = tile * TT + tok;
        const int s   = is_mask ? perm[m] : perm[MASKN + m];
        const int h = s / 576, w = (s % 576) / 24, d = s % 24;
        if (seg == 0) { sH[tok] = h; sW[tok] = w; sD[tok] = d; }
        float4 v;
        if (!is_mask) {
            const int i = seg >> 2, j = seg & 3;
            const size_t xi = (((size_t)(b * 96 + 4 * h + i)) * 96 + (4 * w + j)) * 96 + 4 * d;
            v = *(const float4*)(x + xi);
        } else {
            v = *(const float4*)(mtok + (size_t)m * KDIM + seg * 4);
        }
        const int p = seg * 4;
        ps[p + 0][tok] = v.x; ps[p + 1][tok] = v.y;
        ps[p + 2][tok] = v.z; ps[p + 3][tok] = v.w;
    }
    __syncthreads();

    // ---- GEMM: each thread owns embed dims {tid, tid+256, tid+512},
    //      accumulators hold token PAIRS in packed f32x2; bias folded into init ----
    const unsigned long long B0 = pack2(bias[tid]);
    const unsigned long long B1 = pack2(bias[tid + 256]);
    const unsigned long long B2 = pack2(bias[tid + 512]);
    unsigned long long a0[8], a1[8], a2[8];
    #pragma unroll
    for (int t = 0; t < 8; t++) { a0[t] = B0; a1[t] = B1; a2[t] = B2; }

    const float* wp = W + tid;
    #pragma unroll 4
    for (int k = 0; k < KDIM; k++) {
        const unsigned long long W0 = pack2(wp[k * EDIM]);
        const unsigned long long W1 = pack2(wp[k * EDIM + 256]);
        const unsigned long long W2 = pack2(wp[k * EDIM + 512]);
        const unsigned long long* pp = (const unsigned long long*)ps[k];
        #pragma unroll
        for (int t = 0; t < 8; t++) {
            const unsigned long long pd = pp[t];   // LDS.64 broadcast (token pair)
            fma2(a0[t], pd, W0);
            fma2(a1[t], pd, W1);
            fma2(a2[t], pd, W2);
        }
    }

    // ---- epilogue: unpack, + positional encoding from table ----
    float v0[TT], v1[TT], v2[TT];
    #pragma unroll
    for (int t = 0; t < 8; t++) {
        unpack2(a0[t], v0[2 * t], v0[2 * t + 1]);
        unpack2(a1[t], v1[2 * t], v1[2 * t + 1]);
        unpack2(a2[t], v2[2 * t], v2[2 * t + 1]);
    }

    const int warp = tid >> 5, lane = tid & 31;

    #pragma unroll
    for (int t = 0; t < TT; t++) {
        v0[t] += g_pe[sH[t]][tid];
        v1[t] += g_pe[sW[t]][tid];
        v2[t] += g_pe[sD[t]][tid];

        float sm = v0[t] + v1[t] + v2[t];
        float sq = v0[t] * v0[t] + v1[t] * v1[t] + v2[t] * v2[t];
        #pragma unroll
        for (int off = 16; off > 0; off >>= 1) {
            sm += __shfl_xor_sync(0xffffffffu, sm, off);
            sq += __shfl_xor_sync(0xffffffffu, sq, off);
        }
        if (lane == 0) { redS[t][warp] = sm; redQ[t][warp] = sq; }
    }
    __syncthreads();

    if (tid < TT) {
        float sm = 0.f, sq = 0.f;
        #pragma unroll
        for (int wi = 0; wi < 8; wi++) { sm += redS[tid][wi]; sq += redQ[tid][wi]; }
        const float mn = sm * (1.0f / (float)EDIM);
        const float vr = sq * (1.0f / (float)EDIM) - mn * mn;
        meanv[tid] = mn;
        rstdv[tid] = rsqrtf(vr + 0.001f);
    }
    __syncthreads();

    const float g0 = gamma[tid], g1 = gamma[tid + 256], g2 = gamma[tid + 512];
    const float be0 = beta[tid], be1 = beta[tid + 256], be2 = beta[tid + 512];

    if (!is_mask) {
        float* o = out + ((size_t)b * TOKENS + (size_t)tile * TT) * EDIM + tid;
        #pragma unroll
        for (int t = 0; t < TT; t++) {
            const float mn = meanv[t], rs = rstdv[t];
            o[(size_t)t * EDIM]       = (v0[t] - mn) * rs * g0 + be0;
            o[(size_t)t * EDIM + 256] = (v1[t] - mn) * rs * g1 + be1;
            o[(size_t)t * EDIM + 512] = (v2[t] - mn) * rs * g2 + be2;
        }
    } else {
        float* o = out + ((size_t)UNMASKN + (size_t)tile * TT) * EDIM + tid;
        const size_t bstride = (size_t)TOKENS * EDIM;
        #pragma unroll
        for (int t = 0; t < TT; t++) {
            const float mn = meanv[t], rs = rstdv[t];
            const float o0 = (v0[t] - mn) * rs * g0 + be0;
            const float o1 = (v1[t] - mn) * rs * g1 + be1;
            const float o2 = (v2[t] - mn) * rs * g2 + be2;
            #pragma unroll
            for (int bb = 0; bb < BATCH; bb++) {
                float* op = o + bb * bstride + (size_t)t * EDIM;
                op[0]   = o0;
                op[256] = o1;
                op[512] = o2;
            }
        }
    }
}

extern "C" void kernel_launch(void* const* d_in, const int* in_sizes, int n_in,
                              void* d_out, int out_size) {
    const float* x     = (const float*)d_in[0];
    const float* W     = (const float*)d_in[1];
    const float* bias  = (const float*)d_in[2];
    const float* mtok  = (const float*)d_in[3];
    const float* gamma = (const float*)d_in[4];
    const float* beta  = (const float*)d_in[5];
    const int*   perm  = (const int*)d_in[6];
    float* out = (float*)d_out;

    const long long main_elems = (long long)BATCH * TOKENS * EDIM;  // 42,467,328
    const long long extra = (long long)out_size - main_elems;       // expected 10368 (mask_idx)
    const int n_tail = extra > 0 ? (int)extra : 0;
    const int tail_blocks = (n_tail + NTHREADS - 1) / NTHREADS;

    // init: pe table (24 blocks) + mask_idx tail writes
    init_kernel<<<24 + tail_blocks, NTHREADS>>>(perm, out + main_elems, n_tail);

    embed_kernel<<<BATCH * UTILES + MTILES, NTHREADS>>>(x, W, bias, mtok, gamma, beta, perm, out);
}

// round 3
// speedup vs baseline: 1.3330x; 1.1078x over previous
#include <cuda_runtime.h>

// Problem constants (B=4, 96^3 vol, 4^3 patches, E=768)
#define TOKENS   13824      // 24*24*24
#define MASKN    10368      // 75%
#define UNMASKN  3456
#define EDIM     768
#define KDIM     64
#define TT       16         // tokens per block
#define NTHREADS 256
#define UTILES   (UNMASKN / TT)   // 216
#define MTILES   (MASKN / TT)     // 648
#define BATCH    4
#define LOG2_1E4 13.287712379549449f

// positional-encoding table: g_pe[pos][c] = (c even ? sin : cos)(pos * 10000^-( (c>>1)/128 ))
__device__ float g_pe[24][256];

__device__ __forceinline__ unsigned long long pack2(float a) {
    unsigned long long r;
    asm("mov.b64 %0, {%1, %1};" : "=l"(r) : "f"(a));
    return r;
}
__device__ __forceinline__ void fma2(unsigned long long& acc,
                                     unsigned long long a, unsigned long long b) {
    asm("fma.rn.f32x2 %0, %1, %2, %0;" : "+l"(acc) : "l"(a), "l"(b));
}
__device__ __forceinline__ void unpack2(unsigned long long v, float& lo, float& hi) {
    asm("mov.b64 {%0, %1}, %2;" : "=f"(lo), "=f"(hi) : "l"(v));
}

// Blocks [0,24): fill pe table row = blockIdx.x. Blocks [24,..): write mask_idx tail.
__global__ __launch_bounds__(NTHREADS)
void init_kernel(const int* __restrict__ perm, float* __restrict__ tail_out, int n_tail) {
    const int bi = blockIdx.x, tid = threadIdx.x;
    if (bi < 24) {
        const float invf = exp2f(-(float)(tid >> 1) * (LOG2_1E4 / 128.0f));
        float s, c;
        sincosf((float)bi * invf, &s, &c);
        g_pe[bi][tid] = (tid & 1) ? c : s;
    } else {
        const int i = (bi - 24) * NTHREADS + tid;
        if (i < n_tail) tail_out[i] = (float)perm[i];
    }
}

// One block = 16 tokens x full 768 embed dims (GEMM K=64 + bias + posenc + LayerNorm fused).
// Blocks [0, 864): unmask tokens (per batch). Blocks [864, 1512): mask tokens,
// computed once and written to all 4 batches (batch-invariant incl. LN).
__global__ __launch_bounds__(NTHREADS, 3)
void embed_kernel(const float* __restrict__ x,
                  const float* __restrict__ W,
                  const float* __restrict__ bias,
                  const float* __restrict__ mtok,
                  const float* __restrict__ gamma,
                  const float* __restrict__ beta,
                  const int*   __restrict__ perm,
                  float* __restrict__ out)
{
    __shared__ float ps[KDIM][TT];          // patch tile, k-major so token pairs are contiguous
    __shared__ int   sH[TT], sW[TT], sD[TT];
    __shared__ float redS[TT][9], redQ[TT][9];
    __shared__ float meanv[TT], rstdv[TT];

    const int tid = threadIdx.x;
    const int bi  = blockIdx.x;
    const bool is_mask = bi >= BATCH * UTILES;
    int b = 0, tile;
    if (!is_mask) { b = bi / UTILES; tile = bi % UTILES; }
    else          { tile = bi - BATCH * UTILES; }

    // ---- stage: gather 16 patch rows (64 floats each) into SMEM ----
    {
        const int tok = tid >> 4;     // 0..15
        const int seg = tid & 15;     // 0..15 -> 4 floats each
        const int m   = tile * TT + tok;
        const int s   = is_mask ? perm[m] : perm[MASKN + m];
        const int h = s / 576, w = (s % 576) / 24, d = s % 24;
        if (seg == 0) { sH[tok] = h; sW[tok] = w; sD[tok] = d; }
        float4 v;
        if (!is_mask) {
            const int i = seg >> 2, j = seg & 3;
            const size_t xi = (((size_t)(b * 96 + 4 * h + i)) * 96 + (4 * w + j)) * 96 + 4 * d;
            v = *(const float4*)(x + xi);
        } else {
            v = *(const float4*)(mtok + (size_t)m * KDIM + seg * 4);
        }
        const int p = seg * 4;
        ps[p + 0][tok] = v.x; ps[p + 1][tok] = v.y;
        ps[p + 2][tok] = v.z; ps[p + 3][tok] = v.w;
    }
    __syncthreads();

    // ---- GEMM: each thread owns embed dims {tid, tid+256, tid+512},
    //      accumulators hold token PAIRS in packed f32x2; bias folded into init ----
    const unsigned long long B0 = pack2(bias[tid]);
    const unsigned long long B1 = pack2(bias[tid + 256]);
    const unsigned long long B2 = pack2(bias[tid + 512]);
    unsigned long long a0[8], a1[8], a2[8];
    #pragma unroll
    for (int t = 0; t < 8; t++) { a0[t] = B0; a1[t] = B1; a2[t] = B2; }

    const float* wp = W + tid;
    #pragma unroll 4
    for (int k = 0; k < KDIM; k++) {
        const unsigned long long W0 = pack2(wp[k * EDIM]);
        const unsigned long long W1 = pack2(wp[k * EDIM + 256]);
        const unsigned long long W2 = pack2(wp[k * EDIM + 512]);
        const ulonglong2* pp2 = (const ulonglong2*)ps[k];   // LDS.128 broadcast (4 tokens)
        #pragma unroll
        for (int q = 0; q < 4; q++) {
            const ulonglong2 pd = pp2[q];
            fma2(a0[2 * q],     pd.x, W0);
            fma2(a1[2 * q],     pd.x, W1);
            fma2(a2[2 * q],     pd.x, W2);
            fma2(a0[2 * q + 1], pd.y, W0);
            fma2(a1[2 * q + 1], pd.y, W1);
            fma2(a2[2 * q + 1], pd.y, W2);
        }
    }

    // ---- epilogue: unpack, + positional encoding from table ----
    float v0[TT], v1[TT], v2[TT];
    #pragma unroll
    for (int t = 0; t < 8; t++) {
        unpack2(a0[t], v0[2 * t], v0[2 * t + 1]);
        unpack2(a1[t], v1[2 * t], v1[2 * t + 1]);
        unpack2(a2[t], v2[2 * t], v2[2 * t + 1]);
    }

    const int warp = tid >> 5, lane = tid & 31;

    #pragma unroll
    for (int t = 0; t < TT; t++) {
        v0[t] += __ldg(&g_pe[sH[t]][tid]);
        v1[t] += __ldg(&g_pe[sW[t]][tid]);
        v2[t] += __ldg(&g_pe[sD[t]][tid]);

        float sm = v0[t] + v1[t] + v2[t];
        float sq = v0[t] * v0[t] + v1[t] * v1[t] + v2[t] * v2[t];
        #pragma unroll
        for (int off = 16; off > 0; off >>= 1) {
            sm += __shfl_xor_sync(0xffffffffu, sm, off);
            sq += __shfl_xor_sync(0xffffffffu, sq, off);
        }
        if (lane == 0) { redS[t][warp] = sm; redQ[t][warp] = sq; }
    }
    __syncthreads();

    if (tid < TT) {
        float sm = 0.f, sq = 0.f;
        #pragma unroll
        for (int wi = 0; wi < 8; wi++) { sm += redS[tid][wi]; sq += redQ[tid][wi]; }
        const float mn = sm * (1.0f / (float)EDIM);
        const float vr = sq * (1.0f / (float)EDIM) - mn * mn;
        meanv[tid] = mn;
        rstdv[tid] = rsqrtf(vr + 0.001f);
    }
    __syncthreads();

    const float g0 = gamma[tid], g1 = gamma[tid + 256], g2 = gamma[tid + 512];
    const float be0 = beta[tid], be1 = beta[tid + 256], be2 = beta[tid + 512];

    if (!is_mask) {
        float* o = out + ((size_t)b * TOKENS + (size_t)tile * TT) * EDIM + tid;
        #pragma unroll
        for (int t = 0; t < TT; t++) {
            const float mn = meanv[t], rs = rstdv[t];
            o[(size_t)t * EDIM]       = (v0[t] - mn) * rs * g0 + be0;
            o[(size_t)t * EDIM + 256] = (v1[t] - mn) * rs * g1 + be1;
            o[(size_t)t * EDIM + 512] = (v2[t] - mn) * rs * g2 + be2;
        }
    } else {
        float* o = out + ((size_t)UNMASKN + (size_t)tile * TT) * EDIM + tid;
        const size_t bstride = (size_t)TOKENS * EDIM;
        #pragma unroll
        for (int t = 0; t < TT; t++) {
            const float mn = meanv[t], rs = rstdv[t];
            const float o0 = (v0[t] - mn) * rs * g0 + be0;
            const float o1 = (v1[t] - mn) * rs * g1 + be1;
            const float o2 = (v2[t] - mn) * rs * g2 + be2;
            #pragma unroll
            for (int bb = 0; bb < BATCH; bb++) {
                float* op = o + bb * bstride + (size_t)t * EDIM;
                op[0]   = o0;
                op[256] = o1;
                op[512] = o2;
            }
        }
    }
}

extern "C" void kernel_launch(void* const* d_in, const int* in_sizes, int n_in,
                              void* d_out, int out_size) {
    const float* x     = (const float*)d_in[0];
    const float* W     = (const float*)d_in[1];
    const float* bias  = (const float*)d_in[2];
    const float* mtok  = (const float*)d_in[3];
    const float* gamma = (const float*)d_in[4];
    const float* beta  = (const float*)d_in[5];
    const int*   perm  = (const int*)d_in[6];
    float* out = (float*)d_out;

    const long long main_elems = (long long)BATCH * TOKENS * EDIM;  // 42,467,328
    const long long extra = (long long)out_size - main_elems;       // expected 10368 (mask_idx)
    const int n_tail = extra > 0 ? (int)extra : 0;
    const int tail_blocks = (n_tail + NTHREADS - 1) / NTHREADS;

    // init: pe table (24 blocks) + mask_idx tail writes
    init_kernel<<<24 + tail_blocks, NTHREADS>>>(perm, out + main_elems, n_tail);

    embed_kernel<<<BATCH * UTILES + MTILES, NTHREADS>>>(x, W, bias, mtok, gamma, beta, perm, out);
}

// round 4
// speedup vs baseline: 1.3344x; 1.0011x over previous
#include <cuda_runtime.h>

// Problem constants (B=4, 96^3 vol, 4^3 patches, E=768)
#define TOKENS   13824      // 24*24*24
#define MASKN    10368      // 75%
#define UNMASKN  3456
#define EDIM     768
#define KDIM     64
#define TT       16         // tokens per block
#define NTHREADS 192        // 192 threads x 4 consecutive dims = 768
#define UTILES   (UNMASKN / TT)   // 216
#define MTILES   (MASKN / TT)     // 648
#define BATCH    4
#define PSROW    20         // padded ps row (floats): 80B, 16B-aligned, fewer STS conflicts
#define LOG2_1E4 13.287712379549449f

// positional-encoding table: g_pe[pos][c] = (c even ? sin : cos)(pos * 10000^-( (c>>1)/128 ))
__device__ float g_pe[24][256];

__device__ __forceinline__ unsigned long long pack2(float a) {
    unsigned long long r;
    asm("mov.b64 %0, {%1, %1};" : "=l"(r) : "f"(a));
    return r;
}
__device__ __forceinline__ void fma2(unsigned long long& acc,
                                     unsigned long long a, unsigned long long b) {
    asm("fma.rn.f32x2 %0, %1, %2, %0;" : "+l"(acc) : "l"(a), "l"(b));
}
__device__ __forceinline__ void unpack2(unsigned long long v, float& lo, float& hi) {
    asm("mov.b64 {%0, %1}, %2;" : "=f"(lo), "=f"(hi) : "l"(v));
}

// Blocks [0,24): fill pe table row = blockIdx.x. Blocks [24,..): write mask_idx tail.
__global__ __launch_bounds__(256)
void init_kernel(const int* __restrict__ perm, float* __restrict__ tail_out, int n_tail) {
    const int bi = blockIdx.x, tid = threadIdx.x;
    if (bi < 24) {
        const float invf = exp2f(-(float)(tid >> 1) * (LOG2_1E4 / 128.0f));
        float s, c;
        sincosf((float)bi * invf, &s, &c);
        g_pe[bi][tid] = (tid & 1) ? c : s;
    } else {
        const int i = (bi - 24) * 256 + tid;
        if (i < n_tail) tail_out[i] = (float)perm[i];
    }
}

// One block = 16 tokens x 768 dims. Thread owns dims 4*tid..4*tid+3 (one pe segment).
// Blocks [0, 864): unmask tokens per batch. Blocks [864, 1512): mask tokens,
// computed once, written to all 4 batches (batch-invariant incl. LN).
__global__ __launch_bounds__(NTHREADS, 3)
void embed_kernel(const float* __restrict__ x,
                  const float* __restrict__ W,
                  const float* __restrict__ bias,
                  const float* __restrict__ mtok,
                  const float* __restrict__ gamma,
                  const float* __restrict__ beta,
                  const int*   __restrict__ perm,
                  float* __restrict__ out)
{
    __shared__ float ps[KDIM][PSROW];       // patch tile, k-major; token pairs contiguous
    __shared__ int   sH[TT], sW[TT], sD[TT];
    __shared__ float redS[TT][6], redQ[TT][6];
    __shared__ float meanv[TT], rstdv[TT];

    const int tid = threadIdx.x;
    const int bi  = blockIdx.x;
    const bool is_mask = bi >= BATCH * UTILES;
    int b = 0, tile;
    if (!is_mask) { b = bi / UTILES; tile = bi % UTILES; }
    else          { tile = bi - BATCH * UTILES; }

    // ---- stage: gather 16 patch rows (64 floats each) into SMEM ----
    for (int it = tid; it < TT * 16; it += NTHREADS) {
        const int tok = it & 15;      // consecutive lanes -> consecutive tokens (2-way STS)
        const int seg = it >> 4;      // 0..15 -> 4 floats each
        const int m   = tile * TT + tok;
        const int s   = is_mask ? perm[m] : perm[MASKN + m];
        const int h = s / 576, w = (s % 576) / 24, d = s % 24;
        if (seg == 0) { sH[tok] = h; sW[tok] = w; sD[tok] = d; }
        float4 v;
        if (!is_mask) {
            const int i = seg >> 2, j = seg & 3;
            const size_t xi = (((size_t)(b * 96 + 4 * h + i)) * 96 + (4 * w + j)) * 96 + 4 * d;
            v = *(const float4*)(x + xi);
        } else {
            v = *(const float4*)(mtok + (size_t)m * KDIM + seg * 4);
        }
        const int p = seg * 4;
        ps[p + 0][tok] = v.x; ps[p + 1][tok] = v.y;
        ps[p + 2][tok] = v.z; ps[p + 3][tok] = v.w;
    }
    __syncthreads();

    // ---- GEMM: thread owns 4 consecutive dims; accumulators = token pairs (f32x2) ----
    const float4 b4 = *((const float4*)bias + tid);
    unsigned long long a0[8], a1[8], a2[8], a3[8];
    {
        const unsigned long long B0 = pack2(b4.x), B1 = pack2(b4.y),
                                 B2 = pack2(b4.z), B3 = pack2(b4.w);
        #pragma unroll
        for (int t = 0; t < 8; t++) { a0[t] = B0; a1[t] = B1; a2[t] = B2; a3[t] = B3; }
    }

    const float4* wp4 = (const float4*)W + tid;
    #pragma unroll 2
    for (int k = 0; k < KDIM; k++) {
        const float4 w4 = wp4[k * (EDIM / 4)];
        const unsigned long long W0 = pack2(w4.x), W1 = pack2(w4.y),
                                 W2 = pack2(w4.z), W3 = pack2(w4.w);
        const ulonglong2* pp2 = (const ulonglong2*)ps[k];   // broadcast LDS.128
        #pragma unroll
        for (int q = 0; q < 4; q++) {
            const ulonglong2 pd = pp2[q];
            fma2(a0[2 * q],     pd.x, W0);
            fma2(a1[2 * q],     pd.x, W1);
            fma2(a2[2 * q],     pd.x, W2);
            fma2(a3[2 * q],     pd.x, W3);
            fma2(a0[2 * q + 1], pd.y, W0);
            fma2(a1[2 * q + 1], pd.y, W1);
            fma2(a2[2 * q + 1], pd.y, W2);
            fma2(a3[2 * q + 1], pd.y, W3);
        }
    }

    // ---- epilogue ----
    float v0[TT], v1[TT], v2[TT], v3[TT];
    #pragma unroll
    for (int t = 0; t < 8; t++) {
        unpack2(a0[t], v0[2 * t], v0[2 * t + 1]);
        unpack2(a1[t], v1[2 * t], v1[2 * t + 1]);
        unpack2(a2[t], v2[2 * t], v2[2 * t + 1]);
        unpack2(a3[t], v3[2 * t], v3[2 * t + 1]);
    }

    // thread's 4 dims live in exactly one pe segment: tid<64 -> H, <128 -> W, else D
    const int* sposArr = (tid < 64) ? sH : (tid < 128) ? sW : sD;
    const int pecol = (tid & 63) * 4;
    const int warp = tid >> 5, lane = tid & 31;

    #pragma unroll
    for (int t = 0; t < TT; t++) {
        const float4 pe = __ldg((const float4*)&g_pe[sposArr[t]][pecol]);
        v0[t] += pe.x; v1[t] += pe.y; v2[t] += pe.z; v3[t] += pe.w;

        float sm = v0[t] + v1[t] + v2[t] + v3[t];
        float sq = v0[t] * v0[t] + v1[t] * v1[t] + v2[t] * v2[t] + v3[t] * v3[t];
        #pragma unroll
        for (int off = 16; off > 0; off >>= 1) {
            sm += __shfl_xor_sync(0xffffffffu, sm, off);
            sq += __shfl_xor_sync(0xffffffffu, sq, off);
        }
        if (lane == 0) { redS[t][warp] = sm; redQ[t][warp] = sq; }
    }
    __syncthreads();

    if (tid < TT) {
        float sm = 0.f, sq = 0.f;
        #pragma unroll
        for (int wi = 0; wi < 6; wi++) { sm += redS[tid][wi]; sq += redQ[tid][wi]; }
        const float mn = sm * (1.0f / (float)EDIM);
        const float vr = sq * (1.0f / (float)EDIM) - mn * mn;
        meanv[tid] = mn;
        rstdv[tid] = rsqrtf(vr + 0.001f);
    }
    __syncthreads();

    const float4 g4  = *((const float4*)gamma + tid);
    const float4 be4 = *((const float4*)beta + tid);

    if (!is_mask) {
        float4* o = (float4*)(out + ((size_t)b * TOKENS + (size_t)tile * TT) * EDIM) + tid;
        #pragma unroll
        for (int t = 0; t < TT; t++) {
            const float mn = meanv[t], rs = rstdv[t];
            float4 r;
            r.x = (v0[t] - mn) * rs * g4.x + be4.x;
            r.y = (v1[t] - mn) * rs * g4.y + be4.y;
            r.z = (v2[t] - mn) * rs * g4.z + be4.z;
            r.w = (v3[t] - mn) * rs * g4.w + be4.w;
            o[(size_t)t * (EDIM / 4)] = r;
        }
    } else {
        float4* o = (float4*)(out + ((size_t)UNMASKN + (size_t)tile * TT) * EDIM) + tid;
        const size_t bstride = (size_t)TOKENS * (EDIM / 4);
        #pragma unroll
        for (int t = 0; t < TT; t++) {
            const float mn = meanv[t], rs = rstdv[t];
            float4 r;
            r.x = (v0[t] - mn) * rs * g4.x + be4.x;
            r.y = (v1[t] - mn) * rs * g4.y + be4.y;
            r.z = (v2[t] - mn) * rs * g4.z + be4.z;
            r.w = (v3[t] - mn) * rs * g4.w + be4.w;
            float4* op = o + (size_t)t * (EDIM / 4);
            op[0]           = r;
            op[bstride]     = r;
            op[2 * bstride] = r;
            op[3 * bstride] = r;
        }
    }
}

extern "C" void kernel_launch(void* const* d_in, const int* in_sizes, int n_in,
                              void* d_out, int out_size) {
    const float* x     = (const float*)d_in[0];
    const float* W     = (const float*)d_in[1];
    const float* bias  = (const float*)d_in[2];
    const float* mtok  = (const float*)d_in[3];
    const float* gamma = (const float*)d_in[4];
    const float* beta  = (const float*)d_in[5];
    const int*   perm  = (const int*)d_in[6];
    float* out = (float*)d_out;

    const long long main_elems = (long long)BATCH * TOKENS * EDIM;  // 42,467,328
    const long long extra = (long long)out_size - main_elems;       // expected 10368 (mask_idx)
    const int n_tail = extra > 0 ? (int)extra : 0;
    const int tail_blocks = (n_tail + 255) / 256;

    // init: pe table (24 blocks) + mask_idx tail writes
    init_kernel<<<24 + tail_blocks, 256>>>(perm, out + main_elems, n_tail);

    embed_kernel<<<BATCH * UTILES + MTILES, NTHREADS>>>(x, W, bias, mtok, gamma, beta, perm, out);
}